// round 8
// baseline (speedup 1.0000x reference)
#include <cuda_runtime.h>

#define SEQ    524288
#define IN_D   5
#define HID    10
#define CHUNK  8
#define WARM   12
#define NST    20
#define NBLK   (SEQ / CHUNK / 32)   // 2048 blocks, 32 chunks (lanes) each
#define L2E2   2.8853900817779268f  // 2 * log2(e)

// smem xp layout: [s(8)][jp(5)][m(34)] float2; byte strides: s=1360, jp=272, m=8
#define S_STR  1360
#define JP_STR 272

// ---------------------------------------------------------------------------
// packed f32x2 helpers
// ---------------------------------------------------------------------------
__device__ __forceinline__ unsigned long long ffma2(unsigned long long a,
                                                    unsigned long long b,
                                                    unsigned long long c)
{
    unsigned long long d;
    asm("fma.rn.f32x2 %0, %1, %2, %3;" : "=l"(d) : "l"(a), "l"(b), "l"(c));
    return d;
}
__device__ __forceinline__ unsigned long long add2(unsigned long long a,
                                                   unsigned long long b)
{
    unsigned long long d;
    asm("add.rn.f32x2 %0, %1, %2;" : "=l"(d) : "l"(a), "l"(b));
    return d;
}
__device__ __forceinline__ unsigned long long pack2(float lo, float hi)
{
    unsigned long long d;
    asm("mov.b64 %0, {%1, %2};" : "=l"(d) : "f"(lo), "f"(hi));
    return d;
}
__device__ __forceinline__ void unpack2(unsigned long long v, float& lo, float& hi)
{
    asm("mov.b64 {%0, %1}, %2;" : "=f"(lo), "=f"(hi) : "l"(v));
}
__device__ __forceinline__ float ex2f(float x)
{
    float e; asm("ex2.approx.f32 %0, %1;" : "=f"(e) : "f"(x)); return e;
}
__device__ __forceinline__ float rcpf(float x)
{
    float r; asm("rcp.approx.f32 %0, %1;" : "=f"(r) : "f"(x)); return r;
}

// ---------------------------------------------------------------------------
// One RNN step: consume xq[J]; refill xq[J] from pbase+ROFF (byte offset);
// dual split accumulators; paired-reciprocal tanh with u = -2r factoring.
// ---------------------------------------------------------------------------
#define STEP(J, ROFF, DO_OUT, OI)                                              \
{                                                                              \
    unsigned long long a0[5], a1[5];                                           \
    _Pragma("unroll")                                                          \
    for (int jp = 0; jp < 5; jp++) {                                           \
        a0[jp] = ffma2(wp[jp][0], hd[0], xq[J][jp]);                           \
        a1[jp] = ffma2(wp[jp][5], hd[5], ZERO);                                \
    }                                                                          \
    _Pragma("unroll")                                                          \
    for (int jp = 0; jp < 5; jp++)                                             \
        xq[J][jp] = *reinterpret_cast<const unsigned long long*>(              \
                        pbase + (ROFF) + jp * JP_STR);                         \
    _Pragma("unroll")                                                          \
    for (int k = 1; k < 5; k++) {                                              \
        _Pragma("unroll")                                                      \
        for (int jp = 0; jp < 5; jp++) {                                       \
            a0[jp] = ffma2(wp[jp][k],     hd[k],     a0[jp]);                  \
            a1[jp] = ffma2(wp[jp][k + 5], hd[k + 5], a1[jp]);                  \
        }                                                                      \
    }                                                                          \
    float hh[HID];                                                             \
    _Pragma("unroll")                                                          \
    for (int jp = 0; jp < 5; jp++) {                                           \
        float zl, zh;                                                          \
        unpack2(add2(a0[jp], a1[jp]), zl, zh);                                 \
        const float A = ex2f(zl) + 1.0f;                                       \
        const float B = ex2f(zh) + 1.0f;                                       \
        const float u = -2.0f * rcpf(A * B);                                   \
        hh[2 * jp]     = fmaf(u, B, 1.0f);                                     \
        hh[2 * jp + 1] = fmaf(u, A, 1.0f);                                     \
    }                                                                          \
    _Pragma("unroll")                                                          \
    for (int j = 0; j < HID; j++) hd[j] = pack2(hh[j], hh[j]);                 \
    if (DO_OUT) {                                                              \
        float o = bf;                                                          \
        _Pragma("unroll")                                                      \
        for (int j = 0; j < HID; j++) o = fmaf(wf[j], hh[j], o);               \
        srow[OI] = o;                                                          \
    }                                                                          \
}

// ---------------------------------------------------------------------------
// Fused kernel: one warp = 32 chunks of 8 (one per lane). Stage src window
// (272 timesteps) -> xp in smem -> 12 warmup + 8 output steps -> flush.
// Lane L, step si consumes t_local = L*8 + si  ->  col m = L + (si>>3),
// slot s = si&7. Global t = c0*8 - 12 + t_local (c0 = blockIdx*32).
// ---------------------------------------------------------------------------
__global__ void __launch_bounds__(32, 12) rnn_fused_kernel(
    const float* __restrict__ src,    // (SEQ, 1, IN_D)
    const float* __restrict__ W_ih,   // (HID, IN_D)
    const float* __restrict__ W_hh,   // (HID, HID)
    const float* __restrict__ b_ih,   // (HID,)
    const float* __restrict__ b_hh,   // (HID,)
    const float* __restrict__ W_fc,   // (1, HID)
    const float* __restrict__ b_fc,   // (1,)
    float* __restrict__ out)          // (SEQ,)
{
    __shared__ float2 sxp[8 * 5 * 34];            // 10880 B
    __shared__ alignas(16) float sraw[1360];      // 5440 B; reused for outputs

    const int lane = threadIdx.x;
    const int c0   = blockIdx.x * 32;
    const long tg0 = (long)c0 * 8 - 12;           // window origin timestep

    // ---- per-lane input weights (pre-scaled by 2*log2e) ----
    float wih[HID][IN_D], bias[HID];
#pragma unroll
    for (int j = 0; j < HID; j++) {
        bias[j] = (b_ih[j] + b_hh[j]) * L2E2;
#pragma unroll
        for (int k = 0; k < IN_D; k++) wih[j][k] = W_ih[j * IN_D + k] * L2E2;
    }

    // ---- stage raw src: 340 float4 (zero-filled outside [0, SEQ)) ----
    {
        const long fb = tg0 * IN_D;               // float index, 16B-aligned
        for (int i = lane; i < 340; i += 32) {
            float4 v = make_float4(0.f, 0.f, 0.f, 0.f);
            const long f = fb + (long)i * 4;
            if (f >= 0 && f < (long)SEQ * IN_D)
                v = *reinterpret_cast<const float4*>(src + f);
            reinterpret_cast<float4*>(sraw)[i] = v;
        }
    }
    __syncwarp();

    // ---- compute xp into sxp (zero for t < 0: keeps chunk-0 warmup exact) ----
#pragma unroll 1
    for (int i = 0; i < 9; i++) {
        const int u = lane + 32 * i;
        if (u < 272) {
            const float* sp = sraw + u * IN_D;
            const float s0 = sp[0], s1 = sp[1], s2 = sp[2], s3 = sp[3], s4 = sp[4];
            const bool neg = (tg0 + u) < 0;
            char* dst = reinterpret_cast<char*>(sxp)
                      + (u & 7) * S_STR + (u >> 3) * 8;
#pragma unroll
            for (int jp = 0; jp < 5; jp++) {
                float vl = bias[2 * jp], vh = bias[2 * jp + 1];
                vl = fmaf(s0, wih[2 * jp][0], vl);  vh = fmaf(s0, wih[2 * jp + 1][0], vh);
                vl = fmaf(s1, wih[2 * jp][1], vl);  vh = fmaf(s1, wih[2 * jp + 1][1], vh);
                vl = fmaf(s2, wih[2 * jp][2], vl);  vh = fmaf(s2, wih[2 * jp + 1][2], vh);
                vl = fmaf(s3, wih[2 * jp][3], vl);  vh = fmaf(s3, wih[2 * jp + 1][3], vh);
                vl = fmaf(s4, wih[2 * jp][4], vl);  vh = fmaf(s4, wih[2 * jp + 1][4], vh);
                if (neg) { vl = 0.0f; vh = 0.0f; }
                *reinterpret_cast<float2*>(dst + jp * JP_STR) = make_float2(vl, vh);
            }
        }
    }
    __syncwarp();

    // ---- recurrent weights (packed, pre-scaled) + readout weights ----
    unsigned long long wp[5][HID];
#pragma unroll
    for (int jp = 0; jp < 5; jp++)
#pragma unroll
        for (int k = 0; k < HID; k++)
            wp[jp][k] = pack2(W_hh[(2 * jp) * HID + k] * L2E2,
                              W_hh[(2 * jp + 1) * HID + k] * L2E2);
    float wf[HID];
#pragma unroll
    for (int j = 0; j < HID; j++) wf[j] = W_fc[j];
    const float bf = b_fc[0];
    const unsigned long long ZERO = pack2(0.0f, 0.0f);

    unsigned long long hd[HID];
#pragma unroll
    for (int j = 0; j < HID; j++) hd[j] = ZERO;

    const char* pbase = reinterpret_cast<const char*>(sxp) + lane * 8;
    float* srow = sraw + lane * 9;               // outputs, stride-9 conflict-free

    // depth-2 prefetch: steps 0,1 (slot 0,1; col m = lane)
    unsigned long long xq[2][5];
#pragma unroll
    for (int jp = 0; jp < 5; jp++) {
        xq[0][jp] = *reinterpret_cast<const unsigned long long*>(pbase + 0 * S_STR + jp * JP_STR);
        xq[1][jp] = *reinterpret_cast<const unsigned long long*>(pbase + 1 * S_STR + jp * JP_STR);
    }

    // ---- warmup: 12 steps (si = 0..11) ----
#pragma unroll 1
    for (int si = 0; si < 12; si += 2) {
        const int r0 = ((si + 2) & 7) * S_STR + ((si + 2) >> 3) * 8;
        const int r1 = ((si + 3) & 7) * S_STR + ((si + 3) >> 3) * 8;
        STEP(0, r0, false, 0)
        STEP(1, r1, false, 0)
    }

    // ---- output: 8 steps (si = 12..19); over-refills read valid smem ----
#pragma unroll 1
    for (int si = 12; si < 20; si += 2) {
        const int r0 = ((si + 2) & 7) * S_STR + ((si + 2) >> 3) * 8;
        const int r1 = ((si + 3) & 7) * S_STR + ((si + 3) >> 3) * 8;
        STEP(0, r0, true, si - 12)
        STEP(1, r1, true, si - 11)
    }

    __syncwarp();

    // ---- coalesced flush: this block owns out[blockIdx*256 .. +256) ----
    float* ob = out + (size_t)blockIdx.x * 256;
#pragma unroll
    for (int i = 0; i < 8; i++) {
        const int idx = i * 32 + lane;
        ob[idx] = sraw[(idx >> 3) * 9 + (idx & 7)];
    }
}

// ---------------------------------------------------------------------------
extern "C" void kernel_launch(void* const* d_in, const int* in_sizes, int n_in,
                              void* d_out, int out_size)
{
    const float* src  = (const float*)d_in[0];
    const float* W_ih = (const float*)d_in[1];
    const float* W_hh = (const float*)d_in[2];
    const float* b_ih = (const float*)d_in[3];
    const float* b_hh = (const float*)d_in[4];
    const float* W_fc = (const float*)d_in[5];
    const float* b_fc = (const float*)d_in[6];
    float* out = (float*)d_out;

    rnn_fused_kernel<<<NBLK, 32>>>(src, W_ih, W_hh, b_ih, b_hh, W_fc, b_fc, out);
}